// round 5
// baseline (speedup 1.0000x reference)
#include <cuda_runtime.h>
#include <cstdint>

#define BATCH 64
#define SEQ   4096
#define LBL   128
#define IGN   (-100)
#define NACC  512
#define NBLK  ((BATCH * SEQ) / 32)   // 8192 loss blocks

// Statically initialized so the very first (correctness) run is valid without
// an init kernel. The last loss block restores all state after each launch.
#define R8 SEQ, SEQ, SEQ, SEQ, SEQ, SEQ, SEQ, SEQ
__device__ int g_first_invalid[BATCH] = {R8, R8, R8, R8, R8, R8, R8, R8};
#undef R8
__device__ double   g_acc[NACC];       // zero-init; self-resetting
__device__ unsigned g_done = 0;        // block-completion counter; self-resetting

// Full-chip scan over target (4 MB): 256 blocks x 256 threads, 4 tokens/thread.
__global__ __launch_bounds__(256) void scan_kernel(const int* __restrict__ target) {
    const int base = blockIdx.x * 1024 + threadIdx.x;
    const int4* tg = reinterpret_cast<const int4*>(target);
#pragma unroll
    for (int i = 0; i < 4; i++) {
        const int token = base + i * 256;
        const int4 t = tg[token];
        if (t.x == IGN || t.y == IGN || t.z == IGN || t.w == IGN)
            atomicMin(&g_first_invalid[token >> 12], token & (SEQ - 1));
    }
}

// 4 tokens per warp, 8 lanes per token, 4 x float4 per lane (MLP=5).
// Final reduction fused via fence+counter last-block pattern.
__global__ __launch_bounds__(256) void loss_kernel(
    const float* __restrict__ emit,
    const int*   __restrict__ target,
    float*       __restrict__ out)
{
    const int warp  = threadIdx.x >> 5;
    const int lane  = threadIdx.x & 31;
    const int tg    = lane >> 3;         // token-in-warp 0..3
    const int g     = lane & 7;          // lane-in-group 0..7
    const int token = blockIdx.x * 32 + warp * 4 + tg;
    const int b     = token >> 12;       // SEQ = 4096
    const int s     = token & (SEQ - 1);

    const float4* row = reinterpret_cast<const float4*>(emit + (size_t)token * LBL);
    const float4 v0 = row[g];
    const float4 v1 = row[8 + g];
    const float4 v2 = row[16 + g];
    const float4 v3 = row[24 + g];
    const int4   t  = reinterpret_cast<const int4*>(target)[token];

    float se = 0.0f, st = 0.0f;

#define PASS(P, V)                                                              \
    {                                                                           \
        const float e0 = __expf(V.x), e1 = __expf(V.y),                         \
                    e2 = __expf(V.z), e3 = __expf(V.w);                         \
        se += (e0 + e1) + (e2 + e3);                                            \
        const int base = (P) * 8 + g;                                           \
        if ((t.x >> 2) == base)                                                 \
            st += ((t.x & 3) == 0 ? e0 : (t.x & 3) == 1 ? e1 : (t.x & 3) == 2 ? e2 : e3); \
        if ((t.y >> 2) == base)                                                 \
            st += ((t.y & 3) == 0 ? e0 : (t.y & 3) == 1 ? e1 : (t.y & 3) == 2 ? e2 : e3); \
        if ((t.z >> 2) == base)                                                 \
            st += ((t.z & 3) == 0 ? e0 : (t.z & 3) == 1 ? e1 : (t.z & 3) == 2 ? e2 : e3); \
        if ((t.w >> 2) == base)                                                 \
            st += ((t.w & 3) == 0 ? e0 : (t.w & 3) == 1 ? e1 : (t.w & 3) == 2 ? e2 : e3); \
    }
    PASS(0, v0) PASS(1, v1) PASS(2, v2) PASS(3, v3)
#undef PASS

    // Reduce within the 8-lane group.
#pragma unroll
    for (int o = 1; o <= 4; o <<= 1) {
        se += __shfl_xor_sync(0xffffffffu, se, o);
        st += __shfl_xor_sync(0xffffffffu, st, o);
    }

    const float loss = (s < g_first_invalid[b]) ? (__logf(se) - __logf(st)) : 0.0f;

    __shared__ float part[32];
    __shared__ bool  amLast;
    if (g == 0) part[warp * 4 + tg] = loss;
    __syncthreads();

    if (threadIdx.x < 32) {
        float x = part[threadIdx.x];
#pragma unroll
        for (int o = 16; o; o >>= 1) x += __shfl_xor_sync(0xffffffffu, x, o);
        if (threadIdx.x == 0) {
            atomicAdd(&g_acc[blockIdx.x & (NACC - 1)], (double)x);
            __threadfence();
            amLast = (atomicAdd(&g_done, 1u) == NBLK - 1);
        }
    }
    __syncthreads();

    // Last block: global reduce + restore all state for the next replay.
    if (amLast) {
        const int i = threadIdx.x;                     // 256 threads
        double x = g_acc[i] + g_acc[i + 256];
        g_acc[i] = 0.0;
        g_acc[i + 256] = 0.0;
        if (i < BATCH) g_first_invalid[i] = SEQ;
        if (i == 0) g_done = 0;

        __shared__ double wsum[8];
#pragma unroll
        for (int o = 16; o; o >>= 1) x += __shfl_xor_sync(0xffffffffu, x, o);
        if ((i & 31) == 0) wsum[i >> 5] = x;
        __syncthreads();
        if (i == 0) {
            double sum = 0.0;
#pragma unroll
            for (int w = 0; w < 8; w++) sum += wsum[w];
            out[0] = (float)sum;
        }
    }
}

extern "C" void kernel_launch(void* const* d_in, const int* in_sizes, int n_in,
                              void* d_out, int out_size)
{
    const float* emit   = (const float*)d_in[0];
    const int*   target = (const int*)d_in[1];
    float*       out    = (float*)d_out;

    scan_kernel<<<256, 256>>>(target);
    loss_kernel<<<NBLK, 256>>>(emit, target, out);
}

// round 6
// speedup vs baseline: 1.0702x; 1.0702x over previous
#include <cuda_runtime.h>
#include <cstdint>

#define BATCH 64
#define SEQ   4096
#define LBL   128
#define IGN   (-100)
#define NACC  512
#define NBLK  ((BATCH * SEQ) / 32)   // 8192 loss blocks

// Statically initialized so the first (correctness) run is valid without an
// init kernel. The last loss block restores all state after each launch.
#define R8 SEQ, SEQ, SEQ, SEQ, SEQ, SEQ, SEQ, SEQ
__device__ int g_first_invalid[BATCH] = {R8, R8, R8, R8, R8, R8, R8, R8};
#undef R8
__device__ double   g_acc[NACC];       // zero-init; self-resetting
__device__ unsigned g_done = 0;        // block-completion counter; self-resetting

// Full-chip scan over target (4 MB): 256 blocks x 256 threads, 4 tokens/thread.
__global__ __launch_bounds__(256) void scan_kernel(const int* __restrict__ target) {
    const int base = blockIdx.x * 1024 + threadIdx.x;
    const int4* tg = reinterpret_cast<const int4*>(target);
#pragma unroll
    for (int i = 0; i < 4; i++) {
        const int token = base + i * 256;
        const int4 t = tg[token];
        if (t.x == IGN || t.y == IGN || t.z == IGN || t.w == IGN)
            atomicMin(&g_first_invalid[token >> 12], token & (SEQ - 1));
    }
}

// 4 tokens per warp, 8 lanes per token, 4 x float4 per lane.
// sum_true via direct L1-hit gather instead of ownership select chains.
__global__ __launch_bounds__(256) void loss_kernel(
    const float* __restrict__ emit,
    const int*   __restrict__ target,
    float*       __restrict__ out)
{
    const int warp  = threadIdx.x >> 5;
    const int lane  = threadIdx.x & 31;
    const int tg    = lane >> 3;         // token-in-warp 0..3
    const int g     = lane & 7;          // lane-in-group 0..7
    const int token = blockIdx.x * 32 + warp * 4 + tg;
    const int b     = token >> 12;       // SEQ = 4096
    const int s     = token & (SEQ - 1);

    const float4* row = reinterpret_cast<const float4*>(emit + (size_t)token * LBL);
    const float4 v0 = row[g];
    const float4 v1 = row[8 + g];
    const float4 v2 = row[16 + g];
    const float4 v3 = row[24 + g];

    // sum_true gather: lanes g=0..3 each handle one target index.
    float st = 0.0f;
    if (g < 4) {
        const int idx = target[token * 4 + g] & (LBL - 1);  // clamp sentinel
        st = __expf(emit[(size_t)token * LBL + idx]);       // L1/L2 hit
    }

    float se = 0.0f;
#define PASS(V)                                                     \
    {                                                               \
        const float e0 = __expf(V.x), e1 = __expf(V.y),             \
                    e2 = __expf(V.z), e3 = __expf(V.w);             \
        se += (e0 + e1) + (e2 + e3);                                \
    }
    PASS(v0) PASS(v1) PASS(v2) PASS(v3)
#undef PASS

    // Reduce within the 8-lane group (offsets 1,2,4 stay inside the group).
#pragma unroll
    for (int o = 1; o <= 4; o <<= 1) {
        se += __shfl_xor_sync(0xffffffffu, se, o);
        st += __shfl_xor_sync(0xffffffffu, st, o);
    }

    const float loss = (s < g_first_invalid[b]) ? (__logf(se) - __logf(st)) : 0.0f;

    __shared__ float part[32];
    __shared__ bool  amLast;
    if (g == 0) part[warp * 4 + tg] = loss;
    __syncthreads();

    if (threadIdx.x < 32) {
        float x = part[threadIdx.x];
#pragma unroll
        for (int o = 16; o; o >>= 1) x += __shfl_xor_sync(0xffffffffu, x, o);
        if (threadIdx.x == 0) {
            atomicAdd(&g_acc[blockIdx.x & (NACC - 1)], (double)x);
            __threadfence();
            amLast = (atomicAdd(&g_done, 1u) == NBLK - 1);
        }
    }
    __syncthreads();

    // Last block: global reduce + restore all state for the next replay.
    if (amLast) {
        const int i = threadIdx.x;                     // 256 threads
        double x = g_acc[i] + g_acc[i + 256];
        g_acc[i] = 0.0;
        g_acc[i + 256] = 0.0;
        if (i < BATCH) g_first_invalid[i] = SEQ;
        if (i == 0) g_done = 0;

        __shared__ double wsum[8];
#pragma unroll
        for (int o = 16; o; o >>= 1) x += __shfl_xor_sync(0xffffffffu, x, o);
        if ((i & 31) == 0) wsum[i >> 5] = x;
        __syncthreads();
        if (i == 0) {
            double sum = 0.0;
#pragma unroll
            for (int w = 0; w < 8; w++) sum += wsum[w];
            out[0] = (float)sum;
        }
    }
}

extern "C" void kernel_launch(void* const* d_in, const int* in_sizes, int n_in,
                              void* d_out, int out_size)
{
    const float* emit   = (const float*)d_in[0];
    const int*   target = (const int*)d_in[1];
    float*       out    = (float*)d_out;

    scan_kernel<<<256, 256>>>(target);
    loss_kernel<<<NBLK, 256>>>(emit, target, out);
}

// round 7
// speedup vs baseline: 1.1427x; 1.0678x over previous
#include <cuda_runtime.h>
#include <cstdint>

#define BATCH 64
#define SEQ   4096
#define LBL   128
#define IGN   (-100)
#define NACC  512
#define NBLK  ((BATCH * SEQ) / 64)   // 4096 loss blocks, 64 tokens each

// Statically initialized so the first (correctness) run is valid without an
// init kernel. The last loss block restores all state after each launch.
#define R8 SEQ, SEQ, SEQ, SEQ, SEQ, SEQ, SEQ, SEQ
__device__ int g_first_invalid[BATCH] = {R8, R8, R8, R8, R8, R8, R8, R8};
#undef R8
__device__ double   g_acc[NACC];       // zero-init; self-resetting
__device__ unsigned g_done = 0;        // block-completion counter; self-resetting

// Full-chip scan over target (4 MB): 256 blocks x 256 threads, 4 tokens/thread.
__global__ __launch_bounds__(256) void scan_kernel(const int* __restrict__ target) {
    const int base = blockIdx.x * 1024 + threadIdx.x;
    const int4* tg = reinterpret_cast<const int4*>(target);
#pragma unroll
    for (int i = 0; i < 4; i++) {
        const int token = base + i * 256;
        const int4 t = tg[token];
        if (t.x == IGN || t.y == IGN || t.z == IGN || t.w == IGN)
            atomicMin(&g_first_invalid[token >> 12], token & (SEQ - 1));
    }
}

// 8 tokens per warp (two groups of 4), 8 lanes per token.
// 8 x LDG.128 + 2 target ints batched up front -> MLP ~10 per thread.
__global__ __launch_bounds__(256) void loss_kernel(
    const float* __restrict__ emit,
    const int*   __restrict__ target,
    float*       __restrict__ out)
{
    const int warp   = threadIdx.x >> 5;
    const int lane   = threadIdx.x & 31;
    const int tg     = lane >> 3;        // token-in-group 0..3
    const int g      = lane & 7;         // lane-in-token 0..7
    const int token0 = blockIdx.x * 64 + warp * 8 + tg;
    const int token1 = token0 + 4;
    const int b      = token0 >> 12;     // whole block is one batch row
    const int s0     = token0 & (SEQ - 1);
    const int s1     = token1 & (SEQ - 1);

    // Targets first: starts the gather dependency chain early (L2-hot).
    int t0 = 0, t1 = 0;
    if (g < 4) {
        t0 = target[token0 * 4 + g] & (LBL - 1);
        t1 = target[token1 * 4 + g] & (LBL - 1);
    }

    // 8 independent 16B loads.
    const float4* row0 = reinterpret_cast<const float4*>(emit + (size_t)token0 * LBL);
    const float4* row1 = reinterpret_cast<const float4*>(emit + (size_t)token1 * LBL);
    const float4 a0 = row0[g],      a1 = row0[8 + g];
    const float4 a2 = row0[16 + g], a3 = row0[24 + g];
    const float4 c0 = row1[g],      c1 = row1[8 + g];
    const float4 c2 = row1[16 + g], c3 = row1[24 + g];

    // Gathers (L1 hits on lines just fetched above).
    float st0 = 0.0f, st1 = 0.0f;
    if (g < 4) {
        st0 = __expf(emit[(size_t)token0 * LBL + t0]);
        st1 = __expf(emit[(size_t)token1 * LBL + t1]);
    }

    float se0 = 0.0f, se1 = 0.0f;
#define PASS(ACC, V)                                                \
    {                                                               \
        const float e0 = __expf(V.x), e1 = __expf(V.y),             \
                    e2 = __expf(V.z), e3 = __expf(V.w);             \
        ACC += (e0 + e1) + (e2 + e3);                               \
    }
    PASS(se0, a0) PASS(se0, a1) PASS(se0, a2) PASS(se0, a3)
    PASS(se1, c0) PASS(se1, c1) PASS(se1, c2) PASS(se1, c3)
#undef PASS

    // Reduce within the 8-lane group (offsets 1,2,4 stay inside the group).
#pragma unroll
    for (int o = 1; o <= 4; o <<= 1) {
        se0 += __shfl_xor_sync(0xffffffffu, se0, o);
        st0 += __shfl_xor_sync(0xffffffffu, st0, o);
        se1 += __shfl_xor_sync(0xffffffffu, se1, o);
        st1 += __shfl_xor_sync(0xffffffffu, st1, o);
    }

    __shared__ float part[32];
    __shared__ bool  amLast;
    if (g == 0) {
        const int fi = g_first_invalid[b];
        float loss = 0.0f;
        if (s0 < fi) loss += __logf(se0) - __logf(st0);
        if (s1 < fi) loss += __logf(se1) - __logf(st1);
        part[warp * 4 + tg] = loss;
    }
    __syncthreads();

    if (threadIdx.x < 32) {
        float x = part[threadIdx.x];
#pragma unroll
        for (int o = 16; o; o >>= 1) x += __shfl_xor_sync(0xffffffffu, x, o);
        if (threadIdx.x == 0) {
            atomicAdd(&g_acc[blockIdx.x & (NACC - 1)], (double)x);
            __threadfence();
            amLast = (atomicAdd(&g_done, 1u) == NBLK - 1);
        }
    }
    __syncthreads();

    // Last block: global reduce + restore all state for the next replay.
    if (amLast) {
        const int i = threadIdx.x;                     // 256 threads
        double x = g_acc[i] + g_acc[i + 256];
        g_acc[i] = 0.0;
        g_acc[i + 256] = 0.0;
        if (i < BATCH) g_first_invalid[i] = SEQ;
        if (i == 0) g_done = 0;

        __shared__ double wsum[8];
#pragma unroll
        for (int o = 16; o; o >>= 1) x += __shfl_xor_sync(0xffffffffu, x, o);
        if ((i & 31) == 0) wsum[i >> 5] = x;
        __syncthreads();
        if (i == 0) {
            double sum = 0.0;
#pragma unroll
            for (int w = 0; w < 8; w++) sum += wsum[w];
            out[0] = (float)sum;
        }
    }
}

extern "C" void kernel_launch(void* const* d_in, const int* in_sizes, int n_in,
                              void* d_out, int out_size)
{
    const float* emit   = (const float*)d_in[0];
    const int*   target = (const int*)d_in[1];
    float*       out    = (float*)d_out;

    scan_kernel<<<256, 256>>>(target);
    loss_kernel<<<NBLK, 256>>>(emit, target, out);
}